// round 1
// baseline (speedup 1.0000x reference)
#include <cuda_runtime.h>
#include <stdint.h>

// ---------------------------------------------------------------------------
// TiledFeaturesMap: B=4, N=2048, C=512, FS=1, T_SZ=9, T_STEP=6, T_CUT=2
//
// Per batch: shift coords by per-batch min; 9x9 windows with stride 6; a tile
// is selected iff its center 5x5 contains >=1 point. Output tile (k,c,ty,tx) =
// features[b, point_at(window cell ty,tx), c] or 0.
//
// Output layout assumption: float32 buffer = [ f_ns (K) | f_tiles (K*512*81) ],
// K = out_size / 41473.
// ---------------------------------------------------------------------------

#define NB   4
#define NP   2048          // points per batch
#define NC   512
#define TSZ  9
#define TSTEP 6
#define CELLS (TSZ*TSZ)          // 81
#define TILE_ELEMS (NC*CELLS)    // 41472
#define KMAX 2048

__device__ int   g_slot_batch[KMAX];
__device__ short g_cellmap[KMAX * CELLS];
__device__ int   g_total;

// ---------------------------------------------------------------------------
// Setup: one block, 1024 threads. Builds slot assignment + per-slot cell maps.
// ---------------------------------------------------------------------------
__global__ __launch_bounds__(1024) void setup_kernel(const void* __restrict__ ys_raw,
                                                     const void* __restrict__ xs_raw)
{
    __shared__ short s_yx[NB * NP];         // packed y*128+x (raw, then shifted)
    __shared__ unsigned char s_mask[NB * 512];
    __shared__ int s_scan[2048];            // scan buffer, then slot_of_tile
    __shared__ int s_ymin[NB], s_ymax[NB], s_xmin[NB], s_xmax[NB];
    __shared__ int s_nH[NB], s_nW[NB], s_base[NB + 1];
    __shared__ int s_is64;

    const int tid = threadIdx.x;

    if (tid == 0) s_is64 = 1;
    if (tid < NB) {
        s_ymin[tid] = 1 << 30; s_ymax[tid] = -1;
        s_xmin[tid] = 1 << 30; s_xmax[tid] = -1;
    }
    __syncthreads();

    // ---- dtype detection: if coords are int64 (LE), all odd 32-bit words of
    // the first 8192 words are 0. If int32, they are real coord values (a
    // permutation-derived set can't be all-zero).
    {
        const int* yw = (const int*)ys_raw;
        const int* xw = (const int*)xs_raw;
        int bad = 0;
        for (int i = 2 * tid + 1; i < NB * NP; i += 2048)
            bad |= yw[i] | xw[i];
        if (bad) s_is64 = 0;   // benign race: all writers store 0
    }
    __syncthreads();
    const bool is64 = (s_is64 != 0);

    // ---- load coords, per-batch min/max (warp reduce + one atomic per warp)
    for (int idx = tid; idx < NB * NP; idx += 1024) {
        int y, x;
        if (is64) {
            y = (int)((const long long*)ys_raw)[idx];
            x = (int)((const long long*)xs_raw)[idx];
        } else {
            y = ((const int*)ys_raw)[idx];
            x = ((const int*)xs_raw)[idx];
        }
        const int b = idx >> 11;            // /2048 — warp-uniform (aligned)
        s_yx[idx] = (short)(y * 128 + x);   // y,x in [0,120) fit in 7 bits

        int wymin = __reduce_min_sync(0xffffffffu, y);
        int wymax = __reduce_max_sync(0xffffffffu, y);
        int wxmin = __reduce_min_sync(0xffffffffu, x);
        int wxmax = __reduce_max_sync(0xffffffffu, x);
        if ((tid & 31) == 0) {
            atomicMin(&s_ymin[b], wymin); atomicMax(&s_ymax[b], wymax);
            atomicMin(&s_xmin[b], wxmin); atomicMax(&s_xmax[b], wxmax);
        }
    }
    __syncthreads();

    if (tid < NB) {
        s_nH[tid] = (s_ymax[tid] - s_ymin[tid] + 1) / TSTEP + 1;
        s_nW[tid] = (s_xmax[tid] - s_xmin[tid] + 1) / TSTEP + 1;
    }
    __syncthreads();
    if (tid == 0) {
        s_base[0] = 0;
        for (int b = 0; b < NB; b++) s_base[b + 1] = s_base[b] + s_nH[b] * s_nW[b];
    }
    for (int i = tid; i < NB * 512; i += 1024) s_mask[i] = 0;
    __syncthreads();

    // ---- shift coords; mark center occupancy.
    // Center of tile i covers rows i*6+2 .. i*6+6 (width 5 < stride 6 -> at
    // most one tile per axis): r=y%6: r==1 -> none; r==0 -> tile y/6-1;
    // r in 2..5 -> tile y/6.
    for (int idx = tid; idx < NB * NP; idx += 1024) {
        const int b = idx >> 11;
        const int v = s_yx[idx];
        const int y = (v >> 7) - s_ymin[b];
        const int x = (v & 127) - s_xmin[b];
        s_yx[idx] = (short)(y * 128 + x);

        const int qy = y / 6, ry = y - 6 * qy;
        const int qx = x / 6, rx = x - 6 * qx;
        const int cy = (ry == 1) ? -1 : ((ry == 0) ? qy - 1 : qy);
        const int cx = (rx == 1) ? -1 : ((rx == 0) ? qx - 1 : qx);
        if (cy >= 0 && cx >= 0)
            s_mask[b * 512 + cy * s_nW[b] + cx] = 1;
    }
    __syncthreads();

    const int Ttot = s_base[NB];   // <= 4*21*21 = 1764 < 2048

    // ---- selection flags in global (batch-major, row-major) tile order
    for (int t = tid; t < 2048; t += 1024) {
        int sel = 0;
        if (t < Ttot) {
            const int b = (t >= s_base[3]) ? 3 : (t >= s_base[2]) ? 2
                        : (t >= s_base[1]) ? 1 : 0;
            sel = s_mask[b * 512 + (t - s_base[b])];
        }
        s_scan[t] = sel;
    }
    __syncthreads();

    // ---- inclusive Hillis-Steele scan over 2048 entries (2 per thread)
    for (int off = 1; off < 2048; off <<= 1) {
        const int t0 = tid, t1 = tid + 1024;
        const int v0 = (t0 >= off) ? s_scan[t0 - off] : 0;
        const int v1 = (t1 >= off) ? s_scan[t1 - off] : 0;
        __syncthreads();
        s_scan[t0] += v0; s_scan[t1] += v1;
        __syncthreads();
    }

    const int total = s_scan[Ttot - 1];
    __syncthreads();

    // ---- convert scan -> slot_of_tile (in place), record slot batch
    for (int t = tid; t < 2048; t += 1024) {
        int slotv = -1;
        if (t < Ttot) {
            const int b = (t >= s_base[3]) ? 3 : (t >= s_base[2]) ? 2
                        : (t >= s_base[1]) ? 1 : 0;
            if (s_mask[b * 512 + (t - s_base[b])]) {
                slotv = s_scan[t] - 1;
                g_slot_batch[slotv] = b;
            }
        }
        s_scan[t] = slotv;
    }

    // ---- clear cell maps (full KMAX so stray blocks are deterministic)
    {
        int* cm32 = (int*)g_cellmap;                 // KMAX*81 shorts, even count
        const int n32 = (KMAX * CELLS) / 2;
        for (int i = tid; i < n32; i += 1024) cm32[i] = -1;  // 0xFFFF,0xFFFF
        for (int i = tid; i < KMAX; i += 1024)
            if (s_scan[0] == s_scan[0])              // keep order trivial
                ;                                    // (slot_batch set above for used slots)
    }
    __syncthreads();

    // ---- scatter points into every covering selected tile's cell map.
    // Window membership: i in [ceil((y-8)/6), floor(y/6)] ∩ [0, nH-1].
    for (int idx = tid; idx < NB * NP; idx += 1024) {
        const int b = idx >> 11;
        const int v = s_yx[idx];
        const int y = v >> 7, x = v & 127;
        const int nW = s_nW[b], nH = s_nH[b];
        const int ilo = (y > 8) ? (y - 3) / 6 : 0;   // ceil((y-8)/6) for y>8
        int       ihi = y / 6;  if (ihi > nH - 1) ihi = nH - 1;
        const int jlo = (x > 8) ? (x - 3) / 6 : 0;
        int       jhi = x / 6;  if (jhi > nW - 1) jhi = nW - 1;
        const short n = (short)(idx & (NP - 1));
        for (int i = ilo; i <= ihi; i++)
            for (int j = jlo; j <= jhi; j++) {
                const int slot = s_scan[s_base[b] + i * nW + j];
                if (slot >= 0)
                    g_cellmap[slot * CELLS + (y - i * 6) * TSZ + (x - j * 6)] = n;
            }
    }
    if (tid == 0) g_total = total;
}

// ---------------------------------------------------------------------------
// Main: one block per selected tile. Streams the 41472-float tile with
// float4 stores; occupied cells gather features[b,n,c] (L1/L2 resident).
// ---------------------------------------------------------------------------
__device__ __forceinline__ float tile_val(const float* __restrict__ fb,
                                          const short* cm, int lin)
{
    const unsigned c = (unsigned)lin / 81u;
    const int cell = lin - (int)(c * 81u);
    const int n = cm[cell];
    return (n >= 0) ? fb[(size_t)n * NC + c] : 0.0f;
}

__global__ __launch_bounds__(256) void tiles_kernel(const float* __restrict__ features,
                                                    float* __restrict__ out,
                                                    int K, int ns_count)
{
    const int s = blockIdx.x;
    const int tid = threadIdx.x;

    __shared__ short cmap[CELLS];
    __shared__ int sb;
    if (tid < CELLS) cmap[tid] = g_cellmap[s * CELLS + tid];
    if (tid == 0) {
        sb = g_slot_batch[s];
        if (ns_count > 0) out[s] = (float)sb;    // f_ns
    }
    __syncthreads();

    const float* fb = features + (size_t)sb * (NP * NC);
    const size_t base = (size_t)ns_count + (size_t)s * TILE_ELEMS;

    const int head = (int)((4u - ((unsigned)base & 3u)) & 3u);
    const int nrem = TILE_ELEMS - head;
    const int nb4 = nrem >> 2;
    const int tail = nrem & 3;

    for (int lin = tid; lin < head; lin += 256)
        out[base + lin] = tile_val(fb, cmap, lin);

    for (int k = tid; k < nb4; k += 256) {
        const int lin = head + (k << 2);
        const unsigned c0 = (unsigned)lin / 81u;
        const int cell0 = lin - (int)(c0 * 81u);
        float4 v;
        float* pv = (float*)&v;
#pragma unroll
        for (int e = 0; e < 4; e++) {
            int cc = cell0 + e;
            unsigned ch = c0;
            if (cc >= 81) { cc -= 81; ch++; }
            const int n = cmap[cc];
            pv[e] = (n >= 0) ? fb[(size_t)n * NC + ch] : 0.0f;
        }
        *(float4*)(out + base + lin) = v;
    }

    for (int k = tid; k < tail; k += 256) {
        const int lin = head + (nb4 << 2) + k;
        out[base + lin] = tile_val(fb, cmap, lin);
    }
}

// ---------------------------------------------------------------------------
extern "C" void kernel_launch(void* const* d_in, const int* in_sizes, int n_in,
                              void* d_out, int out_size)
{
    // metadata order: features (4*2048*512 f32), ys, xs. Be robust: the large
    // buffer is features; the other two keep their relative order (ys, xs).
    int fi = 0;
    for (int i = 0; i < n_in; i++)
        if (in_sizes[i] == NB * NP * NC) fi = i;
    const float* features = (const float*)d_in[fi];
    const void* ys = nullptr;
    const void* xs = nullptr;
    for (int i = 0; i < n_in; i++) {
        if (i == fi) continue;
        if (!ys) ys = d_in[i];
        else if (!xs) xs = d_in[i];
    }

    setup_kernel<<<1, 1024>>>(ys, xs);

    // Output packing: [f_ns (K) | f_tiles (K*41472)] => out_size = K*41473.
    // Fallback: tiles-only if that doesn't divide.
    int K, ns_count;
    if (out_size % (TILE_ELEMS + 1) == 0) {
        K = out_size / (TILE_ELEMS + 1);
        ns_count = K;
    } else {
        K = out_size / TILE_ELEMS;
        ns_count = 0;
    }
    if (K <= 0) return;
    if (K > KMAX) K = KMAX;

    tiles_kernel<<<K, 256>>>(features, (float*)d_out, K, ns_count);
}